// round 11
// baseline (speedup 1.0000x reference)
#include <cuda_runtime.h>
#include <cuda_bf16.h>
#include <cstdint>

#define N_NODES 100000
#define N_EDGES 1200000
#define D 64
#define KEEP_PROB 0.7f
#define SCAN_CHUNK 2048
#define NUM_SBLK ((N_NODES + SCAN_CHUNK - 1) / SCAN_CHUNK)  // 49

typedef unsigned long long ull;

// ---- packed f32x2 helpers (Blackwell FFMA2 via PTX; ptxas won't auto-fuse) ----
__device__ __forceinline__ ull pk2(float a, float b) {
    ull r; asm("mov.b64 %0, {%1, %2};" : "=l"(r) : "f"(a), "f"(b)); return r;
}
__device__ __forceinline__ ull fma2(ull a, ull b, ull c) {
    ull d; asm("fma.rn.f32x2 %0, %1, %2, %3;" : "=l"(d) : "l"(a), "l"(b), "l"(c)); return d;
}
__device__ __forceinline__ ull add2(ull a, ull b) {
    ull d; asm("add.rn.f32x2 %0, %1, %2;" : "=l"(d) : "l"(a), "l"(b)); return d;
}
__device__ __forceinline__ ull mul2(ull a, ull b) {
    ull d; asm("mul.rn.f32x2 %0, %1, %2;" : "=l"(d) : "l"(a), "l"(b)); return d;
}
__device__ __forceinline__ void upk2(ull v, float& lo, float& hi) {
    asm("mov.b64 {%0, %1}, %2;" : "=f"(lo), "=f"(hi) : "l"(v));
}

// ---------------------------------------------------------------------------
// Scratch (__device__ globals; zero-initialized at module load).
// Packed: low 32 bits = layer 0, high 32 bits = layer 1.
// INVARIANT: g_cnt == 0 and g_flag == 0 at every kernel_launch entry.
//   - initial state: CUDA zero-inits device globals
//   - each run: scan_fused re-zeros g_cnt after reading; scatter resets g_flag
// ---------------------------------------------------------------------------
__device__ ull  g_cnt[N_NODES];
__device__ ull  g_off[N_NODES + 1];
__device__ ull  g_cur[N_NODES];
__device__ int  g_flag[NUM_SBLK];   // 0=none, 1=aggregate ready, 2=inclusive ready
__device__ ull  g_aggv[NUM_SBLK];
__device__ ull  g_incv[NUM_SBLK];
__device__ int2 g_e0[N_EDGES];
__device__ int2 g_e1[N_EDGES];
__device__ float g_x1[(size_t)N_NODES * D];

// ---------------------------------------------------------------------------
// 1) count kept edges per row for both layers with ONE packed 64-bit atomic
// ---------------------------------------------------------------------------
__global__ void count_kernel(const int* __restrict__ rows,
                             const float* __restrict__ du) {
    int e = blockIdx.x * blockDim.x + threadIdx.x;
    if (e >= N_EDGES) return;
    float u0 = du[e];
    float u1 = du[N_EDGES + e];
    ull add = 0ULL;
    if (u0 + KEEP_PROB >= 1.0f) add += 1ULL;
    if (u1 + KEEP_PROB >= 1.0f) add += (1ULL << 32);
    if (add) atomicAdd(&g_cnt[rows[e]], add);
}

// ---------------------------------------------------------------------------
// 2) single-kernel exclusive scan (decoupled lookback, 49 blocks all resident)
//    Also zeros g_cnt for the next run and initializes the cursors.
// ---------------------------------------------------------------------------
__global__ void __launch_bounds__(256) scan_fused_kernel() {
    __shared__ ull wt[8];
    __shared__ ull blk_exc;
    int tid = threadIdx.x;
    int lane = tid & 31, wid = tid >> 5;
    int bid = blockIdx.x;
    int base = bid * SCAN_CHUNK + tid * 8;

    ull v[8]; ull sum = 0ULL;
    #pragma unroll
    for (int j = 0; j < 8; j++) {
        int idx = base + j;
        if (idx < N_NODES) {
            v[j] = g_cnt[idx];
            g_cnt[idx] = 0ULL;          // re-zero for next run
        } else v[j] = 0ULL;
        sum += v[j];
    }
    // warp inclusive scan of per-thread sums
    ull s = sum;
    #pragma unroll
    for (int o = 1; o < 32; o <<= 1) {
        ull t = __shfl_up_sync(0xffffffffu, s, o);
        if (lane >= o) s += t;
    }
    if (lane == 31) wt[wid] = s;
    __syncthreads();

    if (tid == 0) {
        ull r = 0ULL;
        #pragma unroll
        for (int k = 0; k < 8; k++) { ull t = wt[k]; wt[k] = r; r += t; }
        ull wtot = r;

        volatile int* vf = g_flag;
        volatile ull* va = g_aggv;
        volatile ull* vi = g_incv;
        if (bid == 0) {
            vi[0] = wtot;
            __threadfence();
            vf[0] = 2;
            blk_exc = 0ULL;
        } else {
            va[bid] = wtot;
            __threadfence();
            vf[bid] = 1;
            // lookback
            ull exc = 0ULL;
            int j = bid - 1;
            while (true) {
                int f;
                do { f = vf[j]; } while (f == 0);
                if (f == 2) { exc += vi[j]; break; }
                exc += va[j];
                j--;
            }
            vi[bid] = exc + wtot;
            __threadfence();
            vf[bid] = 2;
            blk_exc = exc;
        }
    }
    __syncthreads();

    ull run = blk_exc + wt[wid] + (s - sum);
    #pragma unroll
    for (int j = 0; j < 8; j++) {
        int idx = base + j;
        if (idx < N_NODES) {
            g_off[idx] = run;
            g_cur[idx] = run;
            if (idx == N_NODES - 1) g_off[N_NODES] = run + v[j];
        }
        run += v[j];
    }
}

// ---------------------------------------------------------------------------
// 3) scatter kept edges into per-layer CSR slots; also resets lookback flags
// ---------------------------------------------------------------------------
__global__ void scatter_kernel(const int* __restrict__ rows,
                               const int* __restrict__ cols,
                               const float* __restrict__ vals,
                               const float* __restrict__ du) {
    if (blockIdx.x == 0 && threadIdx.x < NUM_SBLK) g_flag[threadIdx.x] = 0;
    int e = blockIdx.x * blockDim.x + threadIdx.x;
    if (e >= N_EDGES) return;
    float u0 = du[e];
    float u1 = du[N_EDGES + e];
    bool k0 = (u0 + KEEP_PROB >= 1.0f);
    bool k1 = (u1 + KEEP_PROB >= 1.0f);
    if (!k0 && !k1) return;
    int r = rows[e];
    int c = cols[e];
    float v = vals[e] / KEEP_PROB;
    ull add = (k0 ? 1ULL : 0ULL) + (k1 ? (1ULL << 32) : 0ULL);
    ull old = atomicAdd(&g_cur[r], add);
    int2 pay = make_int2(c, __float_as_int(v));
    if (k0) g_e0[(int)(old & 0xffffffffULL)] = pay;
    if (k1) g_e1[(int)(old >> 32)] = pay;
}

// ---------------------------------------------------------------------------
// FC: register-tiled GEMM with packed FFMA2 (unchanged from round 10).
// ---------------------------------------------------------------------------
__global__ void __launch_bounds__(256) fc3_kernel(
        const float* __restrict__ emb,
        const float* __restrict__ W,
        const float* __restrict__ b,
        float* __restrict__ out) {
    __shared__ float Wt[64 * 68];   // Wt[k*68 + d]
    __shared__ float et[64 * 68];   // et[k*68 + local_node]
    __shared__ float bs[64];

    int tid = threadIdx.x;
    int n0 = blockIdx.x * 64;

    if (tid < 64) bs[tid] = b[tid];
    #pragma unroll
    for (int i = tid; i < 4096; i += 256) {
        int r = i >> 6, k = i & 63;
        Wt[k * 68 + r] = W[i];
        int n = n0 + r;
        et[k * 68 + r] = (n < N_NODES) ? emb[(size_t)n * 64 + k] : 0.0f;
    }
    __syncthreads();

    int tx = tid & 15;
    int ty = tid >> 4;
    int d0 = tx * 4;
    int r0 = ty * 4;

    ull acc01[4], acc23[4];
    #pragma unroll
    for (int a = 0; a < 4; a++) { acc01[a] = 0ULL; acc23[a] = 0ULL; }

    #pragma unroll 4
    for (int k = 0; k < 64; k++) {
        float4 er = *reinterpret_cast<const float4*>(&et[k * 68 + r0]);
        float4 wr = *reinterpret_cast<const float4*>(&Wt[k * 68 + d0]);
        ull w01 = pk2(wr.x, wr.y);
        ull w23 = pk2(wr.z, wr.w);
        float e4[4] = {er.x, er.y, er.z, er.w};
        #pragma unroll
        for (int a = 0; a < 4; a++) {
            ull e2 = pk2(e4[a], e4[a]);
            acc01[a] = fma2(e2, w01, acc01[a]);
            acc23[a] = fma2(e2, w23, acc23[a]);
        }
    }

    #pragma unroll
    for (int a = 0; a < 4; a++) {
        int n = n0 + r0 + a;
        if (n < N_NODES) {
            float4 o;
            upk2(acc01[a], o.x, o.y);
            upk2(acc23[a], o.z, o.w);
            o.x += bs[d0 + 0];
            o.y += bs[d0 + 1];
            o.z += bs[d0 + 2];
            o.w += bs[d0 + 3];
            *reinterpret_cast<float4*>(&out[(size_t)n * 64 + d0]) = o;
        }
    }
}

// ---------------------------------------------------------------------------
// CSR SpMM consume v3: TWO warps per node (contiguous half-split), each lane
// owns 2 dims (f32x2). Halves the per-warp edge chain + tail imbalance.
// Block = 256 threads = 4 nodes x 2 warps. Warp1 dumps to smem, warp0 combines.
// ---------------------------------------------------------------------------
template <int LAYER>
__global__ void __launch_bounds__(256) csr_spmm3_kernel(
        const float* __restrict__ x_ext,
        float* __restrict__ out) {
    __shared__ ull red[4][32];

    int warp = threadIdx.x >> 5;   // 0..7
    int lane = threadIdx.x & 31;
    int nl   = warp >> 1;          // local node 0..3
    int h    = warp & 1;           // half
    int n = blockIdx.x * 4 + nl;

    const float* __restrict__ xf = (LAYER == 0) ? x_ext : g_x1;
    const ull* __restrict__ x2 = reinterpret_cast<const ull*>(xf);
    const int2* __restrict__ ed = (LAYER == 0) ? g_e0 : g_e1;

    ull o0 = g_off[n];
    ull o1 = g_off[n + 1];
    int s, e;
    if (LAYER == 0) { s = (int)(o0 & 0xffffffffULL); e = (int)(o1 & 0xffffffffULL); }
    else            { s = (int)(o0 >> 32);           e = (int)(o1 >> 32);           }

    int len = e - s;
    int mid = s + ((len + 1) >> 1);
    int i   = h ? mid : s;
    int bnd = h ? e : mid;

    ull acc = 0ULL;
    for (; i + 4 <= bnd; i += 4) {
        int2 p0 = ed[i];
        int2 p1 = ed[i + 1];
        int2 p2 = ed[i + 2];
        int2 p3 = ed[i + 3];
        ull xv0 = x2[p0.x * 32 + lane];
        ull xv1 = x2[p1.x * 32 + lane];
        ull xv2 = x2[p2.x * 32 + lane];
        ull xv3 = x2[p3.x * 32 + lane];
        acc = fma2(pk2(__int_as_float(p0.y), __int_as_float(p0.y)), xv0, acc);
        acc = fma2(pk2(__int_as_float(p1.y), __int_as_float(p1.y)), xv1, acc);
        acc = fma2(pk2(__int_as_float(p2.y), __int_as_float(p2.y)), xv2, acc);
        acc = fma2(pk2(__int_as_float(p3.y), __int_as_float(p3.y)), xv3, acc);
    }
    for (; i < bnd; i++) {
        int2 p = ed[i];
        float v = __int_as_float(p.y);
        acc = fma2(pk2(v, v), x2[p.x * 32 + lane], acc);
    }

    if (h) red[nl][lane] = acc;
    __syncthreads();
    if (!h) {
        acc = add2(acc, red[nl][lane]);
        size_t idx = (size_t)n * 32 + lane;
        if (LAYER == 0) {
            reinterpret_cast<ull*>(g_x1)[idx] = acc;
        } else {
            ull* o2 = reinterpret_cast<ull*>(out);
            ull sum = add2(add2(o2[idx], x2[idx]), acc);
            const float third = 1.0f / 3.0f;
            o2[idx] = mul2(sum, pk2(third, third));
        }
    }
}

// ---------------------------------------------------------------------------
extern "C" void kernel_launch(void* const* d_in, const int* in_sizes, int n_in,
                              void* d_out, int out_size) {
    const float* all_emb = (const float*)d_in[0];
    const float* W       = (const float*)d_in[1];
    const float* b       = (const float*)d_in[2];
    const float* vals    = (const float*)d_in[3];
    const float* drop_u  = (const float*)d_in[4];
    const int*   rows    = (const int*)d_in[5];
    const int*   cols    = (const int*)d_in[6];
    float* out = (float*)d_out;

    const int EDGE_BLOCKS = (N_EDGES + 255) / 256;   // 4688

    // Fork: fc is independent of the CSR build; run it on a side stream.
    // (Host objects only; kernel_launch is invoked a handful of times —
    //  correctness + capture — so per-call create is acceptable.)
    cudaStream_t s2;
    cudaStreamCreateWithFlags(&s2, cudaStreamNonBlocking);
    cudaEvent_t evFork, evFc;
    cudaEventCreateWithFlags(&evFork, cudaEventDisableTiming);
    cudaEventCreateWithFlags(&evFc, cudaEventDisableTiming);

    cudaEventRecord(evFork, 0);
    cudaStreamWaitEvent(s2, evFork, 0);
    fc3_kernel<<<(N_NODES + 63) / 64, 256, 0, s2>>>(all_emb, W, b, out);
    cudaEventRecord(evFc, s2);

    // Main stream: CSR build (3 launches) + consume.
    count_kernel<<<EDGE_BLOCKS, 256>>>(rows, drop_u);
    scan_fused_kernel<<<NUM_SBLK, 256>>>();
    scatter_kernel<<<EDGE_BLOCKS, 256>>>(rows, cols, vals, drop_u);

    // layer 0: g_x1 = A0 @ all_emb   (independent of fc)
    csr_spmm3_kernel<0><<<N_NODES / 4, 256>>>(all_emb, out);

    // join fc, then layer 1 + fused finalize: out = (fc + x1 + A1 @ x1) / 3
    cudaStreamWaitEvent(0, evFc, 0);
    csr_spmm3_kernel<1><<<N_NODES / 4, 256>>>(nullptr, out);
}

// round 12
// speedup vs baseline: 1.4178x; 1.4178x over previous
#include <cuda_runtime.h>
#include <cuda_bf16.h>
#include <cstdint>

#define N_NODES 100000
#define N_EDGES 1200000
#define D 64
#define KEEP_PROB 0.7f
#define SCAN_CHUNK 2048
#define NUM_SBLK ((N_NODES + SCAN_CHUNK - 1) / SCAN_CHUNK)  // 49

typedef unsigned long long ull;

// ---- packed f32x2 helpers (Blackwell FFMA2 via PTX; ptxas won't auto-fuse) ----
__device__ __forceinline__ ull pk2(float a, float b) {
    ull r; asm("mov.b64 %0, {%1, %2};" : "=l"(r) : "f"(a), "f"(b)); return r;
}
__device__ __forceinline__ ull fma2(ull a, ull b, ull c) {
    ull d; asm("fma.rn.f32x2 %0, %1, %2, %3;" : "=l"(d) : "l"(a), "l"(b), "l"(c)); return d;
}
__device__ __forceinline__ ull add2(ull a, ull b) {
    ull d; asm("add.rn.f32x2 %0, %1, %2;" : "=l"(d) : "l"(a), "l"(b)); return d;
}
__device__ __forceinline__ ull mul2(ull a, ull b) {
    ull d; asm("mul.rn.f32x2 %0, %1, %2;" : "=l"(d) : "l"(a), "l"(b)); return d;
}
__device__ __forceinline__ void upk2(ull v, float& lo, float& hi) {
    asm("mov.b64 {%0, %1}, %2;" : "=f"(lo), "=f"(hi) : "l"(v));
}

// ---------------------------------------------------------------------------
// Scratch (__device__ globals; zero-initialized at module load).
// Packed: low 32 bits = layer 0, high 32 bits = layer 1.
// INVARIANT at every kernel_launch entry: g_cnt == 0, g_flag == 0.
//   - initial state: CUDA zero-inits device globals
//   - each run: scan_fused re-zeros g_cnt after reading; scatter resets g_flag
// ---------------------------------------------------------------------------
__device__ ull  g_cnt[N_NODES];
__device__ ull  g_off[N_NODES + 1];
__device__ ull  g_cur[N_NODES];
__device__ int  g_flag[NUM_SBLK];   // 0=none, 1=aggregate ready, 2=inclusive ready
__device__ ull  g_aggv[NUM_SBLK];
__device__ ull  g_incv[NUM_SBLK];
__device__ int2 g_e0[N_EDGES];
__device__ int2 g_e1[N_EDGES];
__device__ float g_x1[(size_t)N_NODES * D];

// ---------------------------------------------------------------------------
// 1) count kept edges per row for both layers with ONE packed 64-bit atomic
// ---------------------------------------------------------------------------
__global__ void count_kernel(const int* __restrict__ rows,
                             const float* __restrict__ du) {
    int e = blockIdx.x * blockDim.x + threadIdx.x;
    if (e >= N_EDGES) return;
    float u0 = du[e];
    float u1 = du[N_EDGES + e];
    ull add = 0ULL;
    if (u0 + KEEP_PROB >= 1.0f) add += 1ULL;
    if (u1 + KEEP_PROB >= 1.0f) add += (1ULL << 32);
    if (add) atomicAdd(&g_cnt[rows[e]], add);
}

// ---------------------------------------------------------------------------
// 2) single-kernel exclusive scan (decoupled lookback, 49 blocks all resident)
//    Also zeros g_cnt for the next run and initializes the cursors.
// ---------------------------------------------------------------------------
__global__ void __launch_bounds__(256) scan_fused_kernel() {
    __shared__ ull wt[8];
    __shared__ ull blk_exc;
    int tid = threadIdx.x;
    int lane = tid & 31, wid = tid >> 5;
    int bid = blockIdx.x;
    int base = bid * SCAN_CHUNK + tid * 8;

    ull v[8]; ull sum = 0ULL;
    #pragma unroll
    for (int j = 0; j < 8; j++) {
        int idx = base + j;
        if (idx < N_NODES) {
            v[j] = g_cnt[idx];
            g_cnt[idx] = 0ULL;          // re-zero for next run
        } else v[j] = 0ULL;
        sum += v[j];
    }
    ull s = sum;
    #pragma unroll
    for (int o = 1; o < 32; o <<= 1) {
        ull t = __shfl_up_sync(0xffffffffu, s, o);
        if (lane >= o) s += t;
    }
    if (lane == 31) wt[wid] = s;
    __syncthreads();

    if (tid == 0) {
        ull r = 0ULL;
        #pragma unroll
        for (int k = 0; k < 8; k++) { ull t = wt[k]; wt[k] = r; r += t; }
        ull wtot = r;

        volatile int* vf = g_flag;
        volatile ull* va = g_aggv;
        volatile ull* vi = g_incv;
        if (bid == 0) {
            vi[0] = wtot;
            __threadfence();
            vf[0] = 2;
            blk_exc = 0ULL;
        } else {
            va[bid] = wtot;
            __threadfence();
            vf[bid] = 1;
            ull exc = 0ULL;
            int j = bid - 1;
            while (true) {
                int f;
                do { f = vf[j]; } while (f == 0);
                if (f == 2) { exc += vi[j]; break; }
                exc += va[j];
                j--;
            }
            vi[bid] = exc + wtot;
            __threadfence();
            vf[bid] = 2;
            blk_exc = exc;
        }
    }
    __syncthreads();

    ull run = blk_exc + wt[wid] + (s - sum);
    #pragma unroll
    for (int j = 0; j < 8; j++) {
        int idx = base + j;
        if (idx < N_NODES) {
            g_off[idx] = run;
            g_cur[idx] = run;
            if (idx == N_NODES - 1) g_off[N_NODES] = run + v[j];
        }
        run += v[j];
    }
}

// ---------------------------------------------------------------------------
// 3) scatter kept edges into per-layer CSR slots; also resets lookback flags
// ---------------------------------------------------------------------------
__global__ void scatter_kernel(const int* __restrict__ rows,
                               const int* __restrict__ cols,
                               const float* __restrict__ vals,
                               const float* __restrict__ du) {
    if (blockIdx.x == 0 && threadIdx.x < NUM_SBLK) g_flag[threadIdx.x] = 0;
    int e = blockIdx.x * blockDim.x + threadIdx.x;
    if (e >= N_EDGES) return;
    float u0 = du[e];
    float u1 = du[N_EDGES + e];
    bool k0 = (u0 + KEEP_PROB >= 1.0f);
    bool k1 = (u1 + KEEP_PROB >= 1.0f);
    if (!k0 && !k1) return;
    int r = rows[e];
    int c = cols[e];
    float v = vals[e] / KEEP_PROB;
    ull add = (k0 ? 1ULL : 0ULL) + (k1 ? (1ULL << 32) : 0ULL);
    ull old = atomicAdd(&g_cur[r], add);
    int2 pay = make_int2(c, __float_as_int(v));
    if (k0) g_e0[(int)(old & 0xffffffffULL)] = pay;
    if (k1) g_e1[(int)(old >> 32)] = pay;
}

// ---------------------------------------------------------------------------
// FC: register-tiled GEMM with packed FFMA2 (round-10 winner, unchanged).
// ---------------------------------------------------------------------------
__global__ void __launch_bounds__(256) fc3_kernel(
        const float* __restrict__ emb,
        const float* __restrict__ W,
        const float* __restrict__ b,
        float* __restrict__ out) {
    __shared__ float Wt[64 * 68];
    __shared__ float et[64 * 68];
    __shared__ float bs[64];

    int tid = threadIdx.x;
    int n0 = blockIdx.x * 64;

    if (tid < 64) bs[tid] = b[tid];
    #pragma unroll
    for (int i = tid; i < 4096; i += 256) {
        int r = i >> 6, k = i & 63;
        Wt[k * 68 + r] = W[i];
        int n = n0 + r;
        et[k * 68 + r] = (n < N_NODES) ? emb[(size_t)n * 64 + k] : 0.0f;
    }
    __syncthreads();

    int tx = tid & 15;
    int ty = tid >> 4;
    int d0 = tx * 4;
    int r0 = ty * 4;

    ull acc01[4], acc23[4];
    #pragma unroll
    for (int a = 0; a < 4; a++) { acc01[a] = 0ULL; acc23[a] = 0ULL; }

    #pragma unroll 4
    for (int k = 0; k < 64; k++) {
        float4 er = *reinterpret_cast<const float4*>(&et[k * 68 + r0]);
        float4 wr = *reinterpret_cast<const float4*>(&Wt[k * 68 + d0]);
        ull w01 = pk2(wr.x, wr.y);
        ull w23 = pk2(wr.z, wr.w);
        float e4[4] = {er.x, er.y, er.z, er.w};
        #pragma unroll
        for (int a = 0; a < 4; a++) {
            ull e2 = pk2(e4[a], e4[a]);
            acc01[a] = fma2(e2, w01, acc01[a]);
            acc23[a] = fma2(e2, w23, acc23[a]);
        }
    }

    #pragma unroll
    for (int a = 0; a < 4; a++) {
        int n = n0 + r0 + a;
        if (n < N_NODES) {
            float4 o;
            upk2(acc01[a], o.x, o.y);
            upk2(acc23[a], o.z, o.w);
            o.x += bs[d0 + 0];
            o.y += bs[d0 + 1];
            o.z += bs[d0 + 2];
            o.w += bs[d0 + 3];
            *reinterpret_cast<float4*>(&out[(size_t)n * 64 + d0]) = o;
        }
    }
}

// ---------------------------------------------------------------------------
// CSR SpMM consume v4: ONE WARP per TWO nodes, lane owns 2 dims (f32x2).
// The warp walks both edge lists simultaneously with independent accumulators
// (uniform per-warp branches, no divergence) — doubles gather MLP vs v2
// without any cross-warp sync.
// Block = 256 threads = 8 warps = 16 nodes.
// ---------------------------------------------------------------------------
template <int LAYER>
__global__ void __launch_bounds__(256) csr_spmm4_kernel(
        const float* __restrict__ x_ext,
        float* __restrict__ out) {
    int warp = threadIdx.x >> 5;
    int lane = threadIdx.x & 31;
    int n0 = blockIdx.x * 16 + warp * 2;
    int n1 = n0 + 1;

    const float* __restrict__ xf = (LAYER == 0) ? x_ext : g_x1;
    const ull* __restrict__ x2 = reinterpret_cast<const ull*>(xf);
    const int2* __restrict__ ed = (LAYER == 0) ? g_e0 : g_e1;

    ull oo0 = g_off[n0];
    ull oo1 = g_off[n1];
    ull oo2 = g_off[n1 + 1];
    int s0, e0, s1, e1;
    if (LAYER == 0) {
        s0 = (int)(oo0 & 0xffffffffULL); e0 = (int)(oo1 & 0xffffffffULL);
        s1 = e0;                         e1 = (int)(oo2 & 0xffffffffULL);
    } else {
        s0 = (int)(oo0 >> 32); e0 = (int)(oo1 >> 32);
        s1 = e0;               e1 = (int)(oo2 >> 32);
    }

    ull acc0 = 0ULL, acc1 = 0ULL;
    int i0 = s0, i1 = s1;

    // joint loop: 2 edges of each node per iteration -> 4 gathers in flight
    while (i0 + 2 <= e0 && i1 + 2 <= e1) {
        int2 a0 = ed[i0];
        int2 a1 = ed[i0 + 1];
        int2 b0 = ed[i1];
        int2 b1 = ed[i1 + 1];
        ull xa0 = x2[a0.x * 32 + lane];
        ull xa1 = x2[a1.x * 32 + lane];
        ull xb0 = x2[b0.x * 32 + lane];
        ull xb1 = x2[b1.x * 32 + lane];
        acc0 = fma2(pk2(__int_as_float(a0.y), __int_as_float(a0.y)), xa0, acc0);
        acc0 = fma2(pk2(__int_as_float(a1.y), __int_as_float(a1.y)), xa1, acc0);
        acc1 = fma2(pk2(__int_as_float(b0.y), __int_as_float(b0.y)), xb0, acc1);
        acc1 = fma2(pk2(__int_as_float(b1.y), __int_as_float(b1.y)), xb1, acc1);
        i0 += 2; i1 += 2;
    }
    // drain node 0
    for (; i0 + 4 <= e0; i0 += 4) {
        int2 p0 = ed[i0];
        int2 p1 = ed[i0 + 1];
        int2 p2 = ed[i0 + 2];
        int2 p3 = ed[i0 + 3];
        ull x0 = x2[p0.x * 32 + lane];
        ull x1 = x2[p1.x * 32 + lane];
        ull x2v = x2[p2.x * 32 + lane];
        ull x3 = x2[p3.x * 32 + lane];
        acc0 = fma2(pk2(__int_as_float(p0.y), __int_as_float(p0.y)), x0, acc0);
        acc0 = fma2(pk2(__int_as_float(p1.y), __int_as_float(p1.y)), x1, acc0);
        acc0 = fma2(pk2(__int_as_float(p2.y), __int_as_float(p2.y)), x2v, acc0);
        acc0 = fma2(pk2(__int_as_float(p3.y), __int_as_float(p3.y)), x3, acc0);
    }
    for (; i0 < e0; i0++) {
        int2 p = ed[i0];
        float v = __int_as_float(p.y);
        acc0 = fma2(pk2(v, v), x2[p.x * 32 + lane], acc0);
    }
    // drain node 1
    for (; i1 + 4 <= e1; i1 += 4) {
        int2 p0 = ed[i1];
        int2 p1 = ed[i1 + 1];
        int2 p2 = ed[i1 + 2];
        int2 p3 = ed[i1 + 3];
        ull x0 = x2[p0.x * 32 + lane];
        ull x1 = x2[p1.x * 32 + lane];
        ull x2v = x2[p2.x * 32 + lane];
        ull x3 = x2[p3.x * 32 + lane];
        acc1 = fma2(pk2(__int_as_float(p0.y), __int_as_float(p0.y)), x0, acc1);
        acc1 = fma2(pk2(__int_as_float(p1.y), __int_as_float(p1.y)), x1, acc1);
        acc1 = fma2(pk2(__int_as_float(p2.y), __int_as_float(p2.y)), x2v, acc1);
        acc1 = fma2(pk2(__int_as_float(p3.y), __int_as_float(p3.y)), x3, acc1);
    }
    for (; i1 < e1; i1++) {
        int2 p = ed[i1];
        float v = __int_as_float(p.y);
        acc1 = fma2(pk2(v, v), x2[p.x * 32 + lane], acc1);
    }

    size_t idx0 = (size_t)n0 * 32 + lane;
    size_t idx1 = (size_t)n1 * 32 + lane;
    if (LAYER == 0) {
        ull* x1o = reinterpret_cast<ull*>(g_x1);
        x1o[idx0] = acc0;
        x1o[idx1] = acc1;
    } else {
        ull* o2 = reinterpret_cast<ull*>(out);
        const float third = 1.0f / 3.0f;
        ull th = pk2(third, third);
        ull sum0 = add2(add2(o2[idx0], x2[idx0]), acc0);
        ull sum1 = add2(add2(o2[idx1], x2[idx1]), acc1);
        o2[idx0] = mul2(sum0, th);
        o2[idx1] = mul2(sum1, th);
    }
}

// ---------------------------------------------------------------------------
extern "C" void kernel_launch(void* const* d_in, const int* in_sizes, int n_in,
                              void* d_out, int out_size) {
    const float* all_emb = (const float*)d_in[0];
    const float* W       = (const float*)d_in[1];
    const float* b       = (const float*)d_in[2];
    const float* vals    = (const float*)d_in[3];
    const float* drop_u  = (const float*)d_in[4];
    const int*   rows    = (const int*)d_in[5];
    const int*   cols    = (const int*)d_in[6];
    float* out = (float*)d_out;

    const int EDGE_BLOCKS = (N_EDGES + 255) / 256;   // 4688

    // CSR build (both layers at once, packed u64) — 3 launches
    count_kernel<<<EDGE_BLOCKS, 256>>>(rows, drop_u);
    scan_fused_kernel<<<NUM_SBLK, 256>>>();
    scatter_kernel<<<EDGE_BLOCKS, 256>>>(rows, cols, vals, drop_u);

    // fc -> out (unscaled), register-tiled + FFMA2
    fc3_kernel<<<(N_NODES + 63) / 64, 256>>>(all_emb, W, b, out);

    // layer 0: g_x1 = A0 @ all_emb
    csr_spmm4_kernel<0><<<N_NODES / 16, 256>>>(all_emb, out);
    // layer 1 + fused finalize: out = (fc + x1 + A1 @ x1) / 3
    csr_spmm4_kernel<1><<<N_NODES / 16, 256>>>(nullptr, out);
}